// round 1
// baseline (speedup 1.0000x reference)
#include <cuda_runtime.h>
#include <math_constants.h>

// ---------------------------------------------------------------------------
// PFCAttention  (B=16, H=W=64, C=512, NH=16, hd=32, WS=8, TW=8)
//   tokens = 65536, windows B_ = 1024, N = 64 tokens/window
// Pipeline:
//   1) expand bias tables  lb[h][n][m], gb[h][n][w]
//   2) fold projections:   Wc = [Wl@Wp_top ; Wg@Wp_bot],  bc = bl@Wp_top + bg@Wp_bot + bp
//   3) qkv = x @ qkv_w + qkv_b                       (65536 x 512 x 1536)
//   4) pooled K,V per (b, head, window)
//   5) fused fine+coarse attention -> FG buffer      (65536 x 1024)
//   6) out = FG @ Wc + bc                            (65536 x 1024 x 512)
// ---------------------------------------------------------------------------

#define TOKENS   65536
#define CDIM     512
#define NHEADS   16
#define HD       32
#define NTOK     64     // tokens per window
#define NWIN     64     // windows per image
#define BATCH    16

// ------------------------- device scratch ----------------------------------
__device__ float g_qkv[(size_t)TOKENS * 1536];   // 402 MB
__device__ float g_FG[(size_t)TOKENS * 1024];    // 268 MB  [fine | coarse]
__device__ float g_Kg[BATCH * NHEADS * NWIN * HD];
__device__ float g_Vg[BATCH * NHEADS * NWIN * HD];
__device__ float g_Wc[1024 * 512];
__device__ float g_bc[512];
__device__ float g_lb[NHEADS * NTOK * NTOK];
__device__ float g_gb[NHEADS * NTOK * NWIN];

// ------------------------- bias table expansion ----------------------------
// id in [0,65536): local  (h,n,m);  id in [65536,131072): global (h,n,w)
__global__ void expand_bias_kernel(const float* __restrict__ lt,
                                   const float* __restrict__ gt)
{
    int id = blockIdx.x * 256 + threadIdx.x;      // grid 512 * 256 = 131072
    int which = id >> 16;
    int r = id & 65535;
    int h = r >> 12;
    int n = (r >> 6) & 63;
    int m = r & 63;
    int i1 = n >> 3, j1 = n & 7;
    int i2 = m >> 3, j2 = m & 7;
    // both tables use stride 15:  local (2*WS-1)=15, global (WS+TW-1)=15
    int idx = (i1 - i2 + 7) * 15 + (j1 - j2 + 7);
    if (which == 0) g_lb[r] = lt[idx * 16 + h];
    else            g_gb[r] = gt[idx * 16 + h];
}

// ------------------------- folded bias -------------------------------------
__global__ void fold_bias_kernel(const float* __restrict__ lpb,
                                 const float* __restrict__ gpb,
                                 const float* __restrict__ pfw,
                                 const float* __restrict__ pfb)
{
    int c = blockIdx.x * 128 + threadIdx.x;       // 512 total
    float s = pfb[c];
    for (int j = 0; j < 512; j++) s += lpb[j] * pfw[j * 512 + c];
    for (int j = 0; j < 512; j++) s += gpb[j] * pfw[(512 + j) * 512 + c];
    g_bc[c] = s;
}

// ------------------------- SGEMM: C = A(MxK) @ B(KxN) + bias ---------------
// row-major everywhere; M%128==0, N%128==0, K%8==0 guaranteed by call sites.
__global__ __launch_bounds__(256)
void sgemm_kernel(const float* __restrict__ A,
                  const float* __restrict__ B,
                  const float* __restrict__ bias,
                  float* __restrict__ C,
                  int M, int N, int K)
{
    __shared__ float As[8][128];
    __shared__ float Bs[8][128];

    int tid = threadIdx.x;
    int bx = blockIdx.x, by = blockIdx.y;

    int aRow = tid >> 1;             // 0..127
    int aCol = (tid & 1) * 4;        // 0 or 4
    int bRow = tid >> 5;             // 0..7
    int bCol = (tid & 31) * 4;       // 0..124
    int tr = (tid >> 4) * 8;
    int tc = (tid & 15) * 8;

    const float* Ap = A + (size_t)(by * 128) * K;
    const float* Bp = B + bx * 128;

    float acc[8][8];
    #pragma unroll
    for (int i = 0; i < 8; i++)
        #pragma unroll
        for (int j = 0; j < 8; j++) acc[i][j] = 0.0f;

    for (int k0 = 0; k0 < K; k0 += 8) {
        float4 a = *(const float4*)(Ap + (size_t)aRow * K + k0 + aCol);
        As[aCol + 0][aRow] = a.x;
        As[aCol + 1][aRow] = a.y;
        As[aCol + 2][aRow] = a.z;
        As[aCol + 3][aRow] = a.w;
        *(float4*)&Bs[bRow][bCol] =
            *(const float4*)(Bp + (size_t)(k0 + bRow) * N + bCol);
        __syncthreads();

        #pragma unroll
        for (int kk = 0; kk < 8; kk++) {
            float ar[8], br[8];
            #pragma unroll
            for (int i = 0; i < 8; i++) ar[i] = As[kk][tr + i];
            #pragma unroll
            for (int j = 0; j < 8; j++) br[j] = Bs[kk][tc + j];
            #pragma unroll
            for (int i = 0; i < 8; i++)
                #pragma unroll
                for (int j = 0; j < 8; j++)
                    acc[i][j] += ar[i] * br[j];
        }
        __syncthreads();
    }

    #pragma unroll
    for (int i = 0; i < 8; i++) {
        size_t row = (size_t)(by * 128 + tr + i);
        #pragma unroll
        for (int j = 0; j < 8; j += 4) {
            float4 v;
            v.x = acc[i][j + 0];
            v.y = acc[i][j + 1];
            v.z = acc[i][j + 2];
            v.w = acc[i][j + 3];
            if (bias) {
                int col = bx * 128 + tc + j;
                v.x += bias[col + 0];
                v.y += bias[col + 1];
                v.z += bias[col + 2];
                v.w += bias[col + 3];
            }
            *(float4*)(C + row * N + bx * 128 + tc + j) = v;
        }
    }
}

// ------------------------- pooled K,V --------------------------------------
// block = (b, w); thread = (h, d). Kg[b][h][w][d] = sum_n k[..] * pool_w[n] + pb
__global__ __launch_bounds__(512)
void pool_kernel(const float* __restrict__ qkv,
                 const float* __restrict__ pool_w,
                 const float* __restrict__ pool_b)
{
    __shared__ float pw[64];
    int tid = threadIdx.x;
    if (tid < 64) pw[tid] = pool_w[tid];
    __syncthreads();

    int bw = blockIdx.x;              // b*64 + w
    int h = tid >> 5, d = tid & 31;
    const float* base = qkv + (size_t)bw * 64 * 1536 + h * 32 + d;

    float aK = 0.0f, aV = 0.0f;
    #pragma unroll 8
    for (int n = 0; n < 64; n++) {
        float w = pw[n];
        aK += base[n * 1536 + 512]  * w;
        aV += base[n * 1536 + 1024] * w;
    }
    float pb = pool_b[0];
    int b = bw >> 6, w_ = bw & 63;
    int o = ((b * 16 + h) * 64 + w_) * 32 + d;
    g_Kg[o] = aK + pb;
    g_Vg[o] = aV + pb;
}

// ------------------------- fused fine + coarse attention -------------------
// block = (head h, window b_); 256 threads.
__global__ __launch_bounds__(256)
void attn_kernel(const float* __restrict__ qkv, float* __restrict__ FG)
{
    const int h  = blockIdx.x;
    const int b_ = blockIdx.y;
    const int b  = b_ >> 6;
    const int tid = threadIdx.x;

    __shared__ float sq[64 * 33];
    __shared__ float sk[64 * 33];
    __shared__ float sv[64 * 33];
    __shared__ float sP[64 * 65];

    const float scale = 0.17677669529663688f;   // 32^-0.5

    // ---- load q (scaled), k, v ----
    const float* base = qkv + (size_t)b_ * 64 * 1536 + h * 32;
    #pragma unroll
    for (int i = 0; i < 8; i++) {
        int idx = i * 256 + tid;          // 0..2047
        int n = idx >> 5, d = idx & 31;
        const float* p = base + (size_t)n * 1536 + d;
        sq[n * 33 + d] = p[0] * scale;
        sk[n * 33 + d] = p[512];
        sv[n * 33 + d] = p[1024];
    }
    __syncthreads();

    // ---- S = q k^T + lb ----
    {
        const int tn = (tid >> 4) << 2;
        const int tm = (tid & 15) << 2;
        float acc[4][4];
        #pragma unroll
        for (int i = 0; i < 4; i++)
            #pragma unroll
            for (int j = 0; j < 4; j++) acc[i][j] = 0.0f;
        #pragma unroll
        for (int d = 0; d < 32; d++) {
            float qr[4], kr[4];
            #pragma unroll
            for (int i = 0; i < 4; i++) qr[i] = sq[(tn + i) * 33 + d];
            #pragma unroll
            for (int j = 0; j < 4; j++) kr[j] = sk[(tm + j) * 33 + d];
            #pragma unroll
            for (int i = 0; i < 4; i++)
                #pragma unroll
                for (int j = 0; j < 4; j++) acc[i][j] += qr[i] * kr[j];
        }
        const float* lb = g_lb + h * 4096;
        #pragma unroll
        for (int i = 0; i < 4; i++)
            #pragma unroll
            for (int j = 0; j < 4; j++)
                sP[(tn + i) * 65 + tm + j] = acc[i][j] + lb[(tn + i) * 64 + tm + j];
    }
    __syncthreads();

    // ---- softmax over rows (one thread per row) ----
    if (tid < 64) {
        float mx = -CUDART_INF_F;
        #pragma unroll 8
        for (int m = 0; m < 64; m++) mx = fmaxf(mx, sP[tid * 65 + m]);
        float s = 0.0f;
        #pragma unroll 8
        for (int m = 0; m < 64; m++) {
            float e = __expf(sP[tid * 65 + m] - mx);
            sP[tid * 65 + m] = e;
            s += e;
        }
        float inv = 1.0f / s;
        #pragma unroll 8
        for (int m = 0; m < 64; m++) sP[tid * 65 + m] *= inv;
    }
    __syncthreads();

    // ---- O = P v  -> FG fine half ----
    float* out = FG + (size_t)b_ * 64 * 1024 + h * 32;
    #pragma unroll
    for (int i = 0; i < 8; i++) {
        int idx = i * 256 + tid;
        int n = idx >> 5, d = idx & 31;
        float acc = 0.0f;
        #pragma unroll 8
        for (int m = 0; m < 64; m++) acc += sP[n * 65 + m] * sv[m * 33 + d];
        out[(size_t)n * 1024 + d] = acc;
    }
    __syncthreads();   // sk/sv about to be overwritten

    // ---- coarse: load pooled Kg, Vg for this (b, h) ----
    const float* kg = g_Kg + (size_t)((b * 16 + h) * 64) * 32;
    const float* vg = g_Vg + (size_t)((b * 16 + h) * 64) * 32;
    #pragma unroll
    for (int i = 0; i < 8; i++) {
        int idx = i * 256 + tid;
        int w = idx >> 5, d = idx & 31;
        sk[w * 33 + d] = kg[idx];
        sv[w * 33 + d] = vg[idx];
    }
    __syncthreads();

    // ---- S2 = q Kg^T + gb ----
    {
        const int tn = (tid >> 4) << 2;
        const int tm = (tid & 15) << 2;
        float acc[4][4];
        #pragma unroll
        for (int i = 0; i < 4; i++)
            #pragma unroll
            for (int j = 0; j < 4; j++) acc[i][j] = 0.0f;
        #pragma unroll
        for (int d = 0; d < 32; d++) {
            float qr[4], kr[4];
            #pragma unroll
            for (int i = 0; i < 4; i++) qr[i] = sq[(tn + i) * 33 + d];
            #pragma unroll
            for (int j = 0; j < 4; j++) kr[j] = sk[(tm + j) * 33 + d];
            #pragma unroll
            for (int i = 0; i < 4; i++)
                #pragma unroll
                for (int j = 0; j < 4; j++) acc[i][j] += qr[i] * kr[j];
        }
        const float* gb = g_gb + h * 4096;
        #pragma unroll
        for (int i = 0; i < 4; i++)
            #pragma unroll
            for (int j = 0; j < 4; j++)
                sP[(tn + i) * 65 + tm + j] = acc[i][j] + gb[(tn + i) * 64 + tm + j];
    }
    __syncthreads();

    if (tid < 64) {
        float mx = -CUDART_INF_F;
        #pragma unroll 8
        for (int m = 0; m < 64; m++) mx = fmaxf(mx, sP[tid * 65 + m]);
        float s = 0.0f;
        #pragma unroll 8
        for (int m = 0; m < 64; m++) {
            float e = __expf(sP[tid * 65 + m] - mx);
            sP[tid * 65 + m] = e;
            s += e;
        }
        float inv = 1.0f / s;
        #pragma unroll 8
        for (int m = 0; m < 64; m++) sP[tid * 65 + m] *= inv;
    }
    __syncthreads();

    // ---- O2 = P2 Vg -> FG coarse half ----
    #pragma unroll
    for (int i = 0; i < 8; i++) {
        int idx = i * 256 + tid;
        int n = idx >> 5, d = idx & 31;
        float acc = 0.0f;
        #pragma unroll 8
        for (int m = 0; m < 64; m++) acc += sP[n * 65 + m] * sv[m * 33 + d];
        out[(size_t)n * 1024 + 512 + d] = acc;
    }
}

// ------------------------- launch ------------------------------------------
extern "C" void kernel_launch(void* const* d_in, const int* in_sizes, int n_in,
                              void* d_out, int out_size)
{
    const float* x     = (const float*)d_in[0];
    const float* qkv_w = (const float*)d_in[1];
    const float* qkv_b = (const float*)d_in[2];
    const float* lbt   = (const float*)d_in[3];
    const float* gbt   = (const float*)d_in[4];
    const float* lpw   = (const float*)d_in[5];
    const float* lpb   = (const float*)d_in[6];
    const float* pw    = (const float*)d_in[7];
    const float* pb    = (const float*)d_in[8];
    const float* gpw   = (const float*)d_in[9];
    const float* gpb   = (const float*)d_in[10];
    const float* pfw   = (const float*)d_in[11];
    const float* pfb   = (const float*)d_in[12];
    float* out = (float*)d_out;

    float *qkvbuf, *fgbuf, *wc, *bc;
    cudaGetSymbolAddress((void**)&qkvbuf, g_qkv);
    cudaGetSymbolAddress((void**)&fgbuf,  g_FG);
    cudaGetSymbolAddress((void**)&wc,     g_Wc);
    cudaGetSymbolAddress((void**)&bc,     g_bc);

    // 1) bias tables
    expand_bias_kernel<<<512, 256>>>(lbt, gbt);

    // 2) fold projections into Wc / bc
    sgemm_kernel<<<dim3(4, 4), 256>>>(lpw, pfw,             nullptr, wc,             512, 512, 512);
    sgemm_kernel<<<dim3(4, 4), 256>>>(gpw, pfw + 512 * 512, nullptr, wc + 512 * 512, 512, 512, 512);
    fold_bias_kernel<<<4, 128>>>(lpb, gpb, pfw, pfb);

    // 3) qkv GEMM
    sgemm_kernel<<<dim3(12, 512), 256>>>(x, qkv_w, qkv_b, qkvbuf, TOKENS, 1536, 512);

    // 4) pooled K,V
    pool_kernel<<<1024, 512>>>(qkvbuf, pw, pb);

    // 5) fused fine + coarse attention
    attn_kernel<<<dim3(16, 1024), 256>>>(qkvbuf, fgbuf);

    // 6) final fused projection
    sgemm_kernel<<<dim3(4, 512), 256>>>(fgbuf, wc, bc, out, TOKENS, 512, 1024);
}

// round 6
// speedup vs baseline: 1.9910x; 1.9910x over previous
#include <cuda_runtime.h>
#include <math_constants.h>

// ---------------------------------------------------------------------------
// PFCAttention  (B=16, H=W=64, C=512, NH=16, hd=32, WS=8, TW=8)
// Round 6 (= Round 2 candidate; four broker timeouts, never measured):
// big GEMMs on TF32 tensor cores (mma.sync.m16n8k8), fp32 accumulate.
// ---------------------------------------------------------------------------

#define TOKENS   65536
#define CDIM     512
#define NHEADS   16
#define HD       32
#define NTOK     64
#define NWIN     64
#define BATCH    16

// ------------------------- device scratch ----------------------------------
__device__ float g_qkv[(size_t)TOKENS * 1536];
__device__ float g_FG[(size_t)TOKENS * 1024];
__device__ float g_Kg[BATCH * NHEADS * NWIN * HD];
__device__ float g_Vg[BATCH * NHEADS * NWIN * HD];
__device__ float g_Wc[1024 * 512];
__device__ float g_bc[512];
__device__ float g_lb[NHEADS * NTOK * NTOK];
__device__ float g_gb[NHEADS * NTOK * NWIN];

// ------------------------- helpers -----------------------------------------
__device__ __forceinline__ unsigned f2tf(float f) {
    unsigned u;
    asm("cvt.rna.tf32.f32 %0, %1;" : "=r"(u) : "f"(f));
    return u;
}

__device__ __forceinline__ void mma_tf32(float* c,
                                         unsigned a0, unsigned a1,
                                         unsigned a2, unsigned a3,
                                         unsigned b0, unsigned b1) {
    asm("mma.sync.aligned.m16n8k8.row.col.f32.tf32.tf32.f32 "
        "{%0,%1,%2,%3}, {%4,%5,%6,%7}, {%8,%9}, {%0,%1,%2,%3};"
        : "+f"(c[0]), "+f"(c[1]), "+f"(c[2]), "+f"(c[3])
        : "r"(a0), "r"(a1), "r"(a2), "r"(a3), "r"(b0), "r"(b1));
}

// ------------------------- bias table expansion ----------------------------
__global__ void expand_bias_kernel(const float* __restrict__ lt,
                                   const float* __restrict__ gt)
{
    int id = blockIdx.x * 256 + threadIdx.x;      // 512*256 = 131072
    int which = id >> 16;
    int r = id & 65535;
    int h = r >> 12;
    int n = (r >> 6) & 63;
    int m = r & 63;
    int i1 = n >> 3, j1 = n & 7;
    int i2 = m >> 3, j2 = m & 7;
    int idx = (i1 - i2 + 7) * 15 + (j1 - j2 + 7);
    if (which == 0) g_lb[r] = lt[idx * 16 + h];
    else            g_gb[r] = gt[idx * 16 + h];
}

// ------------------------- folded bias (parallel) --------------------------
__global__ __launch_bounds__(256)
void fold_bias_kernel(const float* __restrict__ lpb,
                      const float* __restrict__ gpb,
                      const float* __restrict__ pfw,
                      const float* __restrict__ pfb)
{
    __shared__ float red[256];
    int c = blockIdx.x;                 // 512 blocks
    int t = threadIdx.x;
    float s = 0.0f;
    for (int j = t; j < 512; j += 256)
        s += lpb[j] * pfw[j * 512 + c] + gpb[j] * pfw[(512 + j) * 512 + c];
    red[t] = s;
    __syncthreads();
    for (int off = 128; off > 0; off >>= 1) {
        if (t < off) red[t] += red[t + off];
        __syncthreads();
    }
    if (t == 0) g_bc[c] = red[0] + pfb[c];
}

// ------------------------- fp32 SGEMM (small fold GEMMs only) --------------
__global__ __launch_bounds__(256)
void sgemm_kernel(const float* __restrict__ A,
                  const float* __restrict__ B,
                  const float* __restrict__ bias,
                  float* __restrict__ C,
                  int M, int N, int K)
{
    __shared__ float As[8][128];
    __shared__ float Bs[8][128];

    int tid = threadIdx.x;
    int bx = blockIdx.x, by = blockIdx.y;

    int aRow = tid >> 1;
    int aCol = (tid & 1) * 4;
    int bRow = tid >> 5;
    int bCol = (tid & 31) * 4;
    int tr = (tid >> 4) * 8;
    int tc = (tid & 15) * 8;

    const float* Ap = A + (size_t)(by * 128) * K;
    const float* Bp = B + bx * 128;

    float acc[8][8];
    #pragma unroll
    for (int i = 0; i < 8; i++)
        #pragma unroll
        for (int j = 0; j < 8; j++) acc[i][j] = 0.0f;

    for (int k0 = 0; k0 < K; k0 += 8) {
        float4 a = *(const float4*)(Ap + (size_t)aRow * K + k0 + aCol);
        As[aCol + 0][aRow] = a.x;
        As[aCol + 1][aRow] = a.y;
        As[aCol + 2][aRow] = a.z;
        As[aCol + 3][aRow] = a.w;
        *(float4*)&Bs[bRow][bCol] =
            *(const float4*)(Bp + (size_t)(k0 + bRow) * N + bCol);
        __syncthreads();

        #pragma unroll
        for (int kk = 0; kk < 8; kk++) {
            float ar[8], br[8];
            #pragma unroll
            for (int i = 0; i < 8; i++) ar[i] = As[kk][tr + i];
            #pragma unroll
            for (int j = 0; j < 8; j++) br[j] = Bs[kk][tc + j];
            #pragma unroll
            for (int i = 0; i < 8; i++)
                #pragma unroll
                for (int j = 0; j < 8; j++)
                    acc[i][j] += ar[i] * br[j];
        }
        __syncthreads();
    }

    #pragma unroll
    for (int i = 0; i < 8; i++) {
        size_t row = (size_t)(by * 128 + tr + i);
        #pragma unroll
        for (int j = 0; j < 8; j += 4) {
            float4 v;
            v.x = acc[i][j + 0];
            v.y = acc[i][j + 1];
            v.z = acc[i][j + 2];
            v.w = acc[i][j + 3];
            if (bias) {
                int col = bx * 128 + tc + j;
                v.x += bias[col + 0];
                v.y += bias[col + 1];
                v.z += bias[col + 2];
                v.w += bias[col + 3];
            }
            *(float4*)(C + row * N + bx * 128 + tc + j) = v;
        }
    }
}

// ------------------------- TF32 tensor-core GEMM ---------------------------
// C(MxN) = A(MxK) @ B(KxN) + bias,  all row-major.  M%128==0, N%128==0, K%32==0.
// 256 threads = 8 warps in 2x4; warp tile 64x32; block tile 128x128, k-tile 32.
__global__ __launch_bounds__(256)
void tf32gemm_kernel(const float* __restrict__ A,
                     const float* __restrict__ B,
                     const float* __restrict__ bias,
                     float* __restrict__ C,
                     int M, int N, int K)
{
    // bank-conflict-free layouts for the mma fragment access pattern:
    //   As[m][k]: stride 36 -> bank=(4m+k)%32
    //   Bs[k][n]: stride 132 -> bank=(4k+n)%32
    __shared__ unsigned As[128][36];
    __shared__ unsigned Bs[32][132];

    const int tid  = threadIdx.x;
    const int warp = tid >> 5, lane = tid & 31;
    const int g = lane >> 2, tig = lane & 3;
    const int wm = warp >> 2, wn = warp & 3;     // 2 x 4 warp grid

    const float* Ap = A + (size_t)(blockIdx.y * 128) * K;
    const float* Bp = B + blockIdx.x * 128;

    const int aRow = tid >> 3, aCol = (tid & 7) * 4;     // rows 0..31 (+i*32)
    const int bRow = tid >> 5, bCol = (tid & 31) * 4;    // rows 0..7  (+i*8)

    float4 pa[4], pb[4];
    #pragma unroll
    for (int i = 0; i < 4; i++)
        pa[i] = *(const float4*)(Ap + (size_t)(aRow + i * 32) * K + aCol);
    #pragma unroll
    for (int i = 0; i < 4; i++)
        pb[i] = *(const float4*)(Bp + (size_t)(bRow + i * 8) * N + bCol);

    float acc[4][4][4];
    #pragma unroll
    for (int mt = 0; mt < 4; mt++)
        #pragma unroll
        for (int nt = 0; nt < 4; nt++)
            #pragma unroll
            for (int e = 0; e < 4; e++) acc[mt][nt][e] = 0.0f;

    for (int k0 = 0; k0 < K; k0 += 32) {
        #pragma unroll
        for (int i = 0; i < 4; i++) {
            unsigned* d = &As[aRow + i * 32][aCol];
            d[0] = f2tf(pa[i].x); d[1] = f2tf(pa[i].y);
            d[2] = f2tf(pa[i].z); d[3] = f2tf(pa[i].w);
        }
        #pragma unroll
        for (int i = 0; i < 4; i++) {
            unsigned* d = &Bs[bRow + i * 8][bCol];
            d[0] = f2tf(pb[i].x); d[1] = f2tf(pb[i].y);
            d[2] = f2tf(pb[i].z); d[3] = f2tf(pb[i].w);
        }
        __syncthreads();

        if (k0 + 32 < K) {
            #pragma unroll
            for (int i = 0; i < 4; i++)
                pa[i] = *(const float4*)(Ap + (size_t)(aRow + i * 32) * K + k0 + 32 + aCol);
            #pragma unroll
            for (int i = 0; i < 4; i++)
                pb[i] = *(const float4*)(Bp + (size_t)(k0 + 32 + bRow + i * 8) * N + bCol);
        }

        #pragma unroll
        for (int ks = 0; ks < 4; ks++) {
            const int kk = ks * 8 + tig;
            unsigned a[4][4], b[4][2];
            #pragma unroll
            for (int mt = 0; mt < 4; mt++) {
                int r = wm * 64 + mt * 16 + g;
                a[mt][0] = As[r][kk];
                a[mt][1] = As[r + 8][kk];
                a[mt][2] = As[r][kk + 4];
                a[mt][3] = As[r + 8][kk + 4];
            }
            #pragma unroll
            for (int nt = 0; nt < 4; nt++) {
                int cidx = wn * 32 + nt * 8 + g;
                b[nt][0] = Bs[kk][cidx];
                b[nt][1] = Bs[kk + 4][cidx];
            }
            #pragma unroll
            for (int mt = 0; mt < 4; mt++)
                #pragma unroll
                for (int nt = 0; nt < 4; nt++)
                    mma_tf32(acc[mt][nt], a[mt][0], a[mt][1], a[mt][2], a[mt][3],
                             b[nt][0], b[nt][1]);
        }
        __syncthreads();
    }

    #pragma unroll
    for (int mt = 0; mt < 4; mt++) {
        int row = blockIdx.y * 128 + wm * 64 + mt * 16 + g;
        #pragma unroll
        for (int nt = 0; nt < 4; nt++) {
            int col = blockIdx.x * 128 + wn * 32 + nt * 8 + tig * 2;
            float b0 = 0.0f, b1 = 0.0f;
            if (bias) { b0 = bias[col]; b1 = bias[col + 1]; }
            float2 v0, v1;
            v0.x = acc[mt][nt][0] + b0; v0.y = acc[mt][nt][1] + b1;
            v1.x = acc[mt][nt][2] + b0; v1.y = acc[mt][nt][3] + b1;
            *(float2*)(C + (size_t)row * N + col) = v0;
            *(float2*)(C + (size_t)(row + 8) * N + col) = v1;
        }
    }
}

// ------------------------- pooled K,V --------------------------------------
__global__ __launch_bounds__(512)
void pool_kernel(const float* __restrict__ qkv,
                 const float* __restrict__ pool_w,
                 const float* __restrict__ pool_b)
{
    __shared__ float pw[64];
    int tid = threadIdx.x;
    if (tid < 64) pw[tid] = pool_w[tid];
    __syncthreads();

    int bw = blockIdx.x;
    int h = tid >> 5, d = tid & 31;
    const float* base = qkv + (size_t)bw * 64 * 1536 + h * 32 + d;

    float aK = 0.0f, aV = 0.0f;
    #pragma unroll 8
    for (int n = 0; n < 64; n++) {
        float w = pw[n];
        aK += base[n * 1536 + 512]  * w;
        aV += base[n * 1536 + 1024] * w;
    }
    float pb = pool_b[0];
    int b = bw >> 6, w_ = bw & 63;
    int o = ((b * 16 + h) * 64 + w_) * 32 + d;
    g_Kg[o] = aK + pb;
    g_Vg[o] = aV + pb;
}

// ------------------------- fused fine + coarse attention -------------------
__global__ __launch_bounds__(256)
void attn_kernel(const float* __restrict__ qkv, float* __restrict__ FG)
{
    const int h  = blockIdx.x;
    const int b_ = blockIdx.y;
    const int b  = b_ >> 6;
    const int tid = threadIdx.x;

    __shared__ float sq[64 * 33];
    __shared__ float sk[64 * 33];
    __shared__ float sv[64 * 33];
    __shared__ float sP[64 * 65];

    const float scale = 0.17677669529663688f;

    const float* base = qkv + (size_t)b_ * 64 * 1536 + h * 32;
    #pragma unroll
    for (int i = 0; i < 8; i++) {
        int idx = i * 256 + tid;
        int n = idx >> 5, d = idx & 31;
        const float* p = base + (size_t)n * 1536 + d;
        sq[n * 33 + d] = p[0] * scale;
        sk[n * 33 + d] = p[512];
        sv[n * 33 + d] = p[1024];
    }
    __syncthreads();

    {
        const int tn = (tid >> 4) << 2;
        const int tm = (tid & 15) << 2;
        float acc[4][4];
        #pragma unroll
        for (int i = 0; i < 4; i++)
            #pragma unroll
            for (int j = 0; j < 4; j++) acc[i][j] = 0.0f;
        #pragma unroll
        for (int d = 0; d < 32; d++) {
            float qr[4], kr[4];
            #pragma unroll
            for (int i = 0; i < 4; i++) qr[i] = sq[(tn + i) * 33 + d];
            #pragma unroll
            for (int j = 0; j < 4; j++) kr[j] = sk[(tm + j) * 33 + d];
            #pragma unroll
            for (int i = 0; i < 4; i++)
                #pragma unroll
                for (int j = 0; j < 4; j++) acc[i][j] += qr[i] * kr[j];
        }
        const float* lb = g_lb + h * 4096;
        #pragma unroll
        for (int i = 0; i < 4; i++)
            #pragma unroll
            for (int j = 0; j < 4; j++)
                sP[(tn + i) * 65 + tm + j] = acc[i][j] + lb[(tn + i) * 64 + tm + j];
    }
    __syncthreads();

    if (tid < 64) {
        float mx = -CUDART_INF_F;
        #pragma unroll 8
        for (int m = 0; m < 64; m++) mx = fmaxf(mx, sP[tid * 65 + m]);
        float s = 0.0f;
        #pragma unroll 8
        for (int m = 0; m < 64; m++) {
            float e = __expf(sP[tid * 65 + m] - mx);
            sP[tid * 65 + m] = e;
            s += e;
        }
        float inv = 1.0f / s;
        #pragma unroll 8
        for (int m = 0; m < 64; m++) sP[tid * 65 + m] *= inv;
    }
    __syncthreads();

    float* out = FG + (size_t)b_ * 64 * 1024 + h * 32;
    #pragma unroll
    for (int i = 0; i < 8; i++) {
        int idx = i * 256 + tid;
        int n = idx >> 5, d = idx & 31;
        float acc = 0.0f;
        #pragma unroll 8
        for (int m = 0; m < 64; m++) acc += sP[n * 65 + m] * sv[m * 33 + d];
        out[(size_t)n * 1024 + d] = acc;
    }
    __syncthreads();

    const float* kg = g_Kg + (size_t)((b * 16 + h) * 64) * 32;
    const float* vg = g_Vg + (size_t)((b * 16 + h) * 64) * 32;
    #pragma unroll
    for (int i = 0; i < 8; i++) {
        int idx = i * 256 + tid;
        int w = idx >> 5, d = idx & 31;
        sk[w * 33 + d] = kg[idx];
        sv[w * 33 + d] = vg[idx];
    }
    __syncthreads();

    {
        const int tn = (tid >> 4) << 2;
        const int tm = (tid & 15) << 2;
        float acc[4][4];
        #pragma unroll
        for (int i = 0; i < 4; i++)
            #pragma unroll
            for (int j = 0; j < 4; j++) acc[i][j] = 0.0f;
        #pragma unroll
        for (int d = 0; d < 32; d++) {
            float qr[4], kr[4];
            #pragma unroll
            for (int i = 0; i < 4; i++) qr[i] = sq[(tn + i) * 33 + d];
            #pragma unroll
            for (int j = 0; j < 4; j++) kr[j] = sk[(tm + j) * 33 + d];
            #pragma unroll
            for (int i = 0; i < 4; i++)
                #pragma unroll
                for (int j = 0; j < 4; j++) acc[i][j] += qr[i] * kr[j];
        }
        const float* gb = g_gb + h * 4096;
        #pragma unroll
        for (int i = 0; i < 4; i++)
            #pragma unroll
            for (int j = 0; j < 4; j++)
                sP[(tn + i) * 65 + tm + j] = acc[i][j] + gb[(tn + i) * 64 + tm + j];
    }
    __syncthreads();

    if (tid < 64) {
        float mx = -CUDART_INF_F;
        #pragma unroll 8
        for (int m = 0; m < 64; m++) mx = fmaxf(mx, sP[tid * 65 + m]);
        float s = 0.0f;
        #pragma unroll 8
        for (int m = 0; m < 64; m++) {
            float e = __expf(sP[tid * 65 + m] - mx);
            sP[tid * 65 + m] = e;
            s += e;
        }
        float inv = 1.0f / s;
        #pragma unroll 8
        for (int m = 0; m < 64; m++) sP[tid * 65 + m] *= inv;
    }
    __syncthreads();

    #pragma unroll
    for (int i = 0; i < 8; i++) {
        int idx = i * 256 + tid;
        int n = idx >> 5, d = idx & 31;
        float acc = 0.0f;
        #pragma unroll 8
        for (int m = 0; m < 64; m++) acc += sP[n * 65 + m] * sv[m * 33 + d];
        out[(size_t)n * 1024 + 512 + d] = acc;
    }
}

// ------------------------- launch ------------------------------------------
extern "C" void kernel_launch(void* const* d_in, const int* in_sizes, int n_in,
                              void* d_out, int out_size)
{
    const float* x     = (const float*)d_in[0];
    const float* qkv_w = (const float*)d_in[1];
    const float* qkv_b = (const float*)d_in[2];
    const float* lbt   = (const float*)d_in[3];
    const float* gbt   = (const float*)d_in[4];
    const float* lpw   = (const float*)d_in[5];
    const float* lpb   = (const float*)d_in[6];
    const float* pw    = (const float*)d_in[7];
    const float* pb    = (const float*)d_in[8];
    const float* gpw   = (const float*)d_in[9];
    const float* gpb   = (const float*)d_in[10];
    const float* pfw   = (const float*)d_in[11];
    const float* pfb   = (const float*)d_in[12];
    float* out = (float*)d_out;

    float *qkvbuf, *fgbuf, *wc, *bc;
    cudaGetSymbolAddress((void**)&qkvbuf, g_qkv);
    cudaGetSymbolAddress((void**)&fgbuf,  g_FG);
    cudaGetSymbolAddress((void**)&wc,     g_Wc);
    cudaGetSymbolAddress((void**)&bc,     g_bc);

    // 1) bias tables
    expand_bias_kernel<<<512, 256>>>(lbt, gbt);

    // 2) fold projections into Wc / bc (fp32 for accuracy)
    sgemm_kernel<<<dim3(4, 4), 256>>>(lpw, pfw,             nullptr, wc,             512, 512, 512);
    sgemm_kernel<<<dim3(4, 4), 256>>>(gpw, pfw + 512 * 512, nullptr, wc + 512 * 512, 512, 512, 512);
    fold_bias_kernel<<<512, 256>>>(lpb, gpb, pfw, pfb);

    // 3) qkv GEMM  (tf32 tensor cores)
    tf32gemm_kernel<<<dim3(12, 512), 256>>>(x, qkv_w, qkv_b, qkvbuf, TOKENS, 1536, 512);

    // 4) pooled K,V
    pool_kernel<<<1024, 512>>>(qkvbuf, pw, pb);

    // 5) fused fine + coarse attention
    attn_kernel<<<dim3(16, 1024), 256>>>(qkvbuf, fgbuf);

    // 6) final fused projection  (tf32 tensor cores)
    tf32gemm_kernel<<<dim3(4, 512), 256>>>(fgbuf, wc, bc, out, TOKENS, 512, 1024);
}

// round 7
// speedup vs baseline: 2.0625x; 1.0359x over previous
#include <cuda_runtime.h>
#include <math_constants.h>

// ---------------------------------------------------------------------------
// PFCAttention  (B=16, H=W=64, C=512, NH=16, hd=32, WS=8, TW=8)
// Round 7: tf32 GEMM mainloop -> 2-stage cp.async pipeline, raw-fp32-as-tf32
// (truncation) operands. Rest unchanged from the 2679.8us winner.
// ---------------------------------------------------------------------------

#define TOKENS   65536
#define CDIM     512
#define NHEADS   16
#define HD       32
#define NTOK     64
#define NWIN     64
#define BATCH    16

// ------------------------- device scratch ----------------------------------
__device__ float g_qkv[(size_t)TOKENS * 1536];
__device__ float g_FG[(size_t)TOKENS * 1024];
__device__ float g_Kg[BATCH * NHEADS * NWIN * HD];
__device__ float g_Vg[BATCH * NHEADS * NWIN * HD];
__device__ float g_Wc[1024 * 512];
__device__ float g_bc[512];
__device__ float g_lb[NHEADS * NTOK * NTOK];
__device__ float g_gb[NHEADS * NTOK * NWIN];

// ------------------------- helpers -----------------------------------------
__device__ __forceinline__ void mma_tf32(float* c,
                                         unsigned a0, unsigned a1,
                                         unsigned a2, unsigned a3,
                                         unsigned b0, unsigned b1) {
    asm("mma.sync.aligned.m16n8k8.row.col.f32.tf32.tf32.f32 "
        "{%0,%1,%2,%3}, {%4,%5,%6,%7}, {%8,%9}, {%0,%1,%2,%3};"
        : "+f"(c[0]), "+f"(c[1]), "+f"(c[2]), "+f"(c[3])
        : "r"(a0), "r"(a1), "r"(a2), "r"(a3), "r"(b0), "r"(b1));
}

__device__ __forceinline__ void cp_async16(unsigned* smem_dst, const float* gsrc) {
    unsigned dst = (unsigned)__cvta_generic_to_shared(smem_dst);
    asm volatile("cp.async.cg.shared.global [%0], [%1], 16;"
                 :: "r"(dst), "l"(gsrc) : "memory");
}

// ------------------------- bias table expansion ----------------------------
__global__ void expand_bias_kernel(const float* __restrict__ lt,
                                   const float* __restrict__ gt)
{
    int id = blockIdx.x * 256 + threadIdx.x;      // 512*256 = 131072
    int which = id >> 16;
    int r = id & 65535;
    int h = r >> 12;
    int n = (r >> 6) & 63;
    int m = r & 63;
    int i1 = n >> 3, j1 = n & 7;
    int i2 = m >> 3, j2 = m & 7;
    int idx = (i1 - i2 + 7) * 15 + (j1 - j2 + 7);
    if (which == 0) g_lb[r] = lt[idx * 16 + h];
    else            g_gb[r] = gt[idx * 16 + h];
}

// ------------------------- folded bias (parallel) --------------------------
__global__ __launch_bounds__(256)
void fold_bias_kernel(const float* __restrict__ lpb,
                      const float* __restrict__ gpb,
                      const float* __restrict__ pfw,
                      const float* __restrict__ pfb)
{
    __shared__ float red[256];
    int c = blockIdx.x;                 // 512 blocks
    int t = threadIdx.x;
    float s = 0.0f;
    for (int j = t; j < 512; j += 256)
        s += lpb[j] * pfw[j * 512 + c] + gpb[j] * pfw[(512 + j) * 512 + c];
    red[t] = s;
    __syncthreads();
    for (int off = 128; off > 0; off >>= 1) {
        if (t < off) red[t] += red[t + off];
        __syncthreads();
    }
    if (t == 0) g_bc[c] = red[0] + pfb[c];
}

// ------------------------- fp32 SGEMM (small fold GEMMs only) --------------
__global__ __launch_bounds__(256)
void sgemm_kernel(const float* __restrict__ A,
                  const float* __restrict__ B,
                  const float* __restrict__ bias,
                  float* __restrict__ C,
                  int M, int N, int K)
{
    __shared__ float As[8][128];
    __shared__ float Bs[8][128];

    int tid = threadIdx.x;
    int bx = blockIdx.x, by = blockIdx.y;

    int aRow = tid >> 1;
    int aCol = (tid & 1) * 4;
    int bRow = tid >> 5;
    int bCol = (tid & 31) * 4;
    int tr = (tid >> 4) * 8;
    int tc = (tid & 15) * 8;

    const float* Ap = A + (size_t)(by * 128) * K;
    const float* Bp = B + bx * 128;

    float acc[8][8];
    #pragma unroll
    for (int i = 0; i < 8; i++)
        #pragma unroll
        for (int j = 0; j < 8; j++) acc[i][j] = 0.0f;

    for (int k0 = 0; k0 < K; k0 += 8) {
        float4 a = *(const float4*)(Ap + (size_t)aRow * K + k0 + aCol);
        As[aCol + 0][aRow] = a.x;
        As[aCol + 1][aRow] = a.y;
        As[aCol + 2][aRow] = a.z;
        As[aCol + 3][aRow] = a.w;
        *(float4*)&Bs[bRow][bCol] =
            *(const float4*)(Bp + (size_t)(k0 + bRow) * N + bCol);
        __syncthreads();

        #pragma unroll
        for (int kk = 0; kk < 8; kk++) {
            float ar[8], br[8];
            #pragma unroll
            for (int i = 0; i < 8; i++) ar[i] = As[kk][tr + i];
            #pragma unroll
            for (int j = 0; j < 8; j++) br[j] = Bs[kk][tc + j];
            #pragma unroll
            for (int i = 0; i < 8; i++)
                #pragma unroll
                for (int j = 0; j < 8; j++)
                    acc[i][j] += ar[i] * br[j];
        }
        __syncthreads();
    }

    #pragma unroll
    for (int i = 0; i < 8; i++) {
        size_t row = (size_t)(by * 128 + tr + i);
        #pragma unroll
        for (int j = 0; j < 8; j += 4) {
            float4 v;
            v.x = acc[i][j + 0];
            v.y = acc[i][j + 1];
            v.z = acc[i][j + 2];
            v.w = acc[i][j + 3];
            if (bias) {
                int col = bx * 128 + tc + j;
                v.x += bias[col + 0];
                v.y += bias[col + 1];
                v.z += bias[col + 2];
                v.w += bias[col + 3];
            }
            *(float4*)(C + row * N + bx * 128 + tc + j) = v;
        }
    }
}

// ------------------------- TF32 tensor-core GEMM (cp.async 2-stage) --------
// C(MxN) = A(MxK) @ B(KxN) + bias, row-major. M%128==0, N%128==0, K%32==0.
// 256 threads = 8 warps in 2x4; warp tile 64x32; block tile 128x128, k-tile 32.
// Operands are raw fp32 bit patterns consumed as tf32 (HW truncation).
#define ASZ (128 * 36)
#define BSZ (32 * 132)
#define TF32GEMM_SMEM ((2 * ASZ + 2 * BSZ) * 4)

__global__ __launch_bounds__(256)
void tf32gemm_kernel(const float* __restrict__ A,
                     const float* __restrict__ B,
                     const float* __restrict__ bias,
                     float* __restrict__ C,
                     int M, int N, int K)
{
    // layout: A stage0 | A stage1 | B stage0 | B stage1
    // As[m][k]: stride 36 -> conflict-free (bank = 4g+tig on fragment reads)
    // Bs[k][n]: stride 132 -> conflict-free (bank = 4tig+g)
    extern __shared__ unsigned smem[];

    const int tid  = threadIdx.x;
    const int warp = tid >> 5, lane = tid & 31;
    const int g = lane >> 2, tig = lane & 3;
    const int wm = warp >> 2, wn = warp & 3;     // 2 x 4 warp grid

    const float* Ap = A + (size_t)(blockIdx.y * 128) * K;
    const float* Bp = B + blockIdx.x * 128;

    const int aRow = tid >> 3, aCol = (tid & 7) * 4;     // A: rows 0..31 (+i*32)
    const int bRow = tid >> 5, bCol = (tid & 31) * 4;    // B: rows 0..7  (+i*8)

    float acc[4][4][4];
    #pragma unroll
    for (int mt = 0; mt < 4; mt++)
        #pragma unroll
        for (int nt = 0; nt < 4; nt++)
            #pragma unroll
            for (int e = 0; e < 4; e++) acc[mt][nt][e] = 0.0f;

    const int NK = K >> 5;

    // prologue: stage 0 loads for tile 0
    {
        unsigned* As0 = smem;
        unsigned* Bs0 = smem + 2 * ASZ;
        #pragma unroll
        for (int i = 0; i < 4; i++)
            cp_async16(&As0[(aRow + i * 32) * 36 + aCol],
                       Ap + (size_t)(aRow + i * 32) * K + aCol);
        #pragma unroll
        for (int i = 0; i < 4; i++)
            cp_async16(&Bs0[(bRow + i * 8) * 132 + bCol],
                       Bp + (size_t)(bRow + i * 8) * N + bCol);
        asm volatile("cp.async.commit_group;" ::: "memory");
    }

    for (int kt = 0; kt < NK; kt++) {
        const int cur = kt & 1;
        if (kt + 1 < NK) {
            const int nxt = cur ^ 1;
            const int k0 = (kt + 1) << 5;
            unsigned* Asn = smem + nxt * ASZ;
            unsigned* Bsn = smem + 2 * ASZ + nxt * BSZ;
            #pragma unroll
            for (int i = 0; i < 4; i++)
                cp_async16(&Asn[(aRow + i * 32) * 36 + aCol],
                           Ap + (size_t)(aRow + i * 32) * K + k0 + aCol);
            #pragma unroll
            for (int i = 0; i < 4; i++)
                cp_async16(&Bsn[(bRow + i * 8) * 132 + bCol],
                           Bp + (size_t)(k0 + bRow + i * 8) * N + bCol);
            asm volatile("cp.async.commit_group;" ::: "memory");
            asm volatile("cp.async.wait_group 1;" ::: "memory");
        } else {
            asm volatile("cp.async.wait_group 0;" ::: "memory");
        }
        __syncthreads();

        const unsigned* Asb = smem + cur * ASZ;
        const unsigned* Bsb = smem + 2 * ASZ + cur * BSZ;

        #pragma unroll
        for (int ks = 0; ks < 4; ks++) {
            const int kk = ks * 8 + tig;
            unsigned a[4][4], b[4][2];
            #pragma unroll
            for (int mt = 0; mt < 4; mt++) {
                int r = wm * 64 + mt * 16 + g;
                a[mt][0] = Asb[r * 36 + kk];
                a[mt][1] = Asb[(r + 8) * 36 + kk];
                a[mt][2] = Asb[r * 36 + kk + 4];
                a[mt][3] = Asb[(r + 8) * 36 + kk + 4];
            }
            #pragma unroll
            for (int nt = 0; nt < 4; nt++) {
                int cidx = wn * 32 + nt * 8 + g;
                b[nt][0] = Bsb[kk * 132 + cidx];
                b[nt][1] = Bsb[(kk + 4) * 132 + cidx];
            }
            #pragma unroll
            for (int mt = 0; mt < 4; mt++)
                #pragma unroll
                for (int nt = 0; nt < 4; nt++)
                    mma_tf32(acc[mt][nt], a[mt][0], a[mt][1], a[mt][2], a[mt][3],
                             b[nt][0], b[nt][1]);
        }
        __syncthreads();   // protect cur before iteration kt+1 re-issues into it
    }

    // epilogue
    #pragma unroll
    for (int mt = 0; mt < 4; mt++) {
        int row = blockIdx.y * 128 + wm * 64 + mt * 16 + g;
        #pragma unroll
        for (int nt = 0; nt < 4; nt++) {
            int col = blockIdx.x * 128 + wn * 32 + nt * 8 + tig * 2;
            float b0 = 0.0f, b1 = 0.0f;
            if (bias) { b0 = bias[col]; b1 = bias[col + 1]; }
            float2 v0, v1;
            v0.x = acc[mt][nt][0] + b0; v0.y = acc[mt][nt][1] + b1;
            v1.x = acc[mt][nt][2] + b0; v1.y = acc[mt][nt][3] + b1;
            *(float2*)(C + (size_t)row * N + col) = v0;
            *(float2*)(C + (size_t)(row + 8) * N + col) = v1;
        }
    }
}

// ------------------------- pooled K,V --------------------------------------
__global__ __launch_bounds__(512)
void pool_kernel(const float* __restrict__ qkv,
                 const float* __restrict__ pool_w,
                 const float* __restrict__ pool_b)
{
    __shared__ float pw[64];
    int tid = threadIdx.x;
    if (tid < 64) pw[tid] = pool_w[tid];
    __syncthreads();

    int bw = blockIdx.x;
    int h = tid >> 5, d = tid & 31;
    const float* base = qkv + (size_t)bw * 64 * 1536 + h * 32 + d;

    float aK = 0.0f, aV = 0.0f;
    #pragma unroll 8
    for (int n = 0; n < 64; n++) {
        float w = pw[n];
        aK += base[n * 1536 + 512]  * w;
        aV += base[n * 1536 + 1024] * w;
    }
    float pb = pool_b[0];
    int b = bw >> 6, w_ = bw & 63;
    int o = ((b * 16 + h) * 64 + w_) * 32 + d;
    g_Kg[o] = aK + pb;
    g_Vg[o] = aV + pb;
}

// ------------------------- fused fine + coarse attention -------------------
__global__ __launch_bounds__(256)
void attn_kernel(const float* __restrict__ qkv, float* __restrict__ FG)
{
    const int h  = blockIdx.x;
    const int b_ = blockIdx.y;
    const int b  = b_ >> 6;
    const int tid = threadIdx.x;

    __shared__ float sq[64 * 33];
    __shared__ float sk[64 * 33];
    __shared__ float sv[64 * 33];
    __shared__ float sP[64 * 65];

    const float scale = 0.17677669529663688f;

    const float* base = qkv + (size_t)b_ * 64 * 1536 + h * 32;
    #pragma unroll
    for (int i = 0; i < 8; i++) {
        int idx = i * 256 + tid;
        int n = idx >> 5, d = idx & 31;
        const float* p = base + (size_t)n * 1536 + d;
        sq[n * 33 + d] = p[0] * scale;
        sk[n * 33 + d] = p[512];
        sv[n * 33 + d] = p[1024];
    }
    __syncthreads();

    {
        const int tn = (tid >> 4) << 2;
        const int tm = (tid & 15) << 2;
        float acc[4][4];
        #pragma unroll
        for (int i = 0; i < 4; i++)
            #pragma unroll
            for (int j = 0; j < 4; j++) acc[i][j] = 0.0f;
        #pragma unroll
        for (int d = 0; d < 32; d++) {
            float qr[4], kr[4];
            #pragma unroll
            for (int i = 0; i < 4; i++) qr[i] = sq[(tn + i) * 33 + d];
            #pragma unroll
            for (int j = 0; j < 4; j++) kr[j] = sk[(tm + j) * 33 + d];
            #pragma unroll
            for (int i = 0; i < 4; i++)
                #pragma unroll
                for (int j = 0; j < 4; j++) acc[i][j] += qr[i] * kr[j];
        }
        const float* lb = g_lb + h * 4096;
        #pragma unroll
        for (int i = 0; i < 4; i++)
            #pragma unroll
            for (int j = 0; j < 4; j++)
                sP[(tn + i) * 65 + tm + j] = acc[i][j] + lb[(tn + i) * 64 + tm + j];
    }
    __syncthreads();

    if (tid < 64) {
        float mx = -CUDART_INF_F;
        #pragma unroll 8
        for (int m = 0; m < 64; m++) mx = fmaxf(mx, sP[tid * 65 + m]);
        float s = 0.0f;
        #pragma unroll 8
        for (int m = 0; m < 64; m++) {
            float e = __expf(sP[tid * 65 + m] - mx);
            sP[tid * 65 + m] = e;
            s += e;
        }
        float inv = 1.0f / s;
        #pragma unroll 8
        for (int m = 0; m < 64; m++) sP[tid * 65 + m] *= inv;
    }
    __syncthreads();

    float* out = FG + (size_t)b_ * 64 * 1024 + h * 32;
    #pragma unroll
    for (int i = 0; i < 8; i++) {
        int idx = i * 256 + tid;
        int n = idx >> 5, d = idx & 31;
        float acc = 0.0f;
        #pragma unroll 8
        for (int m = 0; m < 64; m++) acc += sP[n * 65 + m] * sv[m * 33 + d];
        out[(size_t)n * 1024 + d] = acc;
    }
    __syncthreads();

    const float* kg = g_Kg + (size_t)((b * 16 + h) * 64) * 32;
    const float* vg = g_Vg + (size_t)((b * 16 + h) * 64) * 32;
    #pragma unroll
    for (int i = 0; i < 8; i++) {
        int idx = i * 256 + tid;
        int w = idx >> 5, d = idx & 31;
        sk[w * 33 + d] = kg[idx];
        sv[w * 33 + d] = vg[idx];
    }
    __syncthreads();

    {
        const int tn = (tid >> 4) << 2;
        const int tm = (tid & 15) << 2;
        float acc[4][4];
        #pragma unroll
        for (int i = 0; i < 4; i++)
            #pragma unroll
            for (int j = 0; j < 4; j++) acc[i][j] = 0.0f;
        #pragma unroll
        for (int d = 0; d < 32; d++) {
            float qr[4], kr[4];
            #pragma unroll
            for (int i = 0; i < 4; i++) qr[i] = sq[(tn + i) * 33 + d];
            #pragma unroll
            for (int j = 0; j < 4; j++) kr[j] = sk[(tm + j) * 33 + d];
            #pragma unroll
            for (int i = 0; i < 4; i++)
                #pragma unroll
                for (int j = 0; j < 4; j++) acc[i][j] += qr[i] * kr[j];
        }
        const float* gb = g_gb + h * 4096;
        #pragma unroll
        for (int i = 0; i < 4; i++)
            #pragma unroll
            for (int j = 0; j < 4; j++)
                sP[(tn + i) * 65 + tm + j] = acc[i][j] + gb[(tn + i) * 64 + tm + j];
    }
    __syncthreads();

    if (tid < 64) {
        float mx = -CUDART_INF_F;
        #pragma unroll 8
        for (int m = 0; m < 64; m++) mx = fmaxf(mx, sP[tid * 65 + m]);
        float s = 0.0f;
        #pragma unroll 8
        for (int m = 0; m < 64; m++) {
            float e = __expf(sP[tid * 65 + m] - mx);
            sP[tid * 65 + m] = e;
            s += e;
        }
        float inv = 1.0f / s;
        #pragma unroll 8
        for (int m = 0; m < 64; m++) sP[tid * 65 + m] *= inv;
    }
    __syncthreads();

    #pragma unroll
    for (int i = 0; i < 8; i++) {
        int idx = i * 256 + tid;
        int n = idx >> 5, d = idx & 31;
        float acc = 0.0f;
        #pragma unroll 8
        for (int m = 0; m < 64; m++) acc += sP[n * 65 + m] * sv[m * 33 + d];
        out[(size_t)n * 1024 + 512 + d] = acc;
    }
}

// ------------------------- launch ------------------------------------------
extern "C" void kernel_launch(void* const* d_in, const int* in_sizes, int n_in,
                              void* d_out, int out_size)
{
    const float* x     = (const float*)d_in[0];
    const float* qkv_w = (const float*)d_in[1];
    const float* qkv_b = (const float*)d_in[2];
    const float* lbt   = (const float*)d_in[3];
    const float* gbt   = (const float*)d_in[4];
    const float* lpw   = (const float*)d_in[5];
    const float* lpb   = (const float*)d_in[6];
    const float* pw    = (const float*)d_in[7];
    const float* pb    = (const float*)d_in[8];
    const float* gpw   = (const float*)d_in[9];
    const float* gpb   = (const float*)d_in[10];
    const float* pfw   = (const float*)d_in[11];
    const float* pfb   = (const float*)d_in[12];
    float* out = (float*)d_out;

    float *qkvbuf, *fgbuf, *wc, *bc;
    cudaGetSymbolAddress((void**)&qkvbuf, g_qkv);
    cudaGetSymbolAddress((void**)&fgbuf,  g_FG);
    cudaGetSymbolAddress((void**)&wc,     g_Wc);
    cudaGetSymbolAddress((void**)&bc,     g_bc);

    // allow 70.7 KB dynamic smem for the pipelined GEMM (attr set, not an alloc)
    cudaFuncSetAttribute(tf32gemm_kernel,
                         cudaFuncAttributeMaxDynamicSharedMemorySize, TF32GEMM_SMEM);

    // 1) bias tables
    expand_bias_kernel<<<512, 256>>>(lbt, gbt);

    // 2) fold projections into Wc / bc (fp32 for accuracy)
    sgemm_kernel<<<dim3(4, 4), 256>>>(lpw, pfw,             nullptr, wc,             512, 512, 512);
    sgemm_kernel<<<dim3(4, 4), 256>>>(gpw, pfw + 512 * 512, nullptr, wc + 512 * 512, 512, 512, 512);
    fold_bias_kernel<<<512, 256>>>(lpb, gpb, pfw, pfb);

    // 3) qkv GEMM  (tf32 tensor cores, cp.async pipeline)
    tf32gemm_kernel<<<dim3(12, 512), 256, TF32GEMM_SMEM>>>(x, qkv_w, qkv_b, qkvbuf,
                                                           TOKENS, 1536, 512);

    // 4) pooled K,V
    pool_kernel<<<1024, 512>>>(qkvbuf, pw, pb);

    // 5) fused fine + coarse attention
    attn_kernel<<<dim3(16, 1024), 256>>>(qkvbuf, fgbuf);

    // 6) final fused projection  (tf32 tensor cores, cp.async pipeline)
    tf32gemm_kernel<<<dim3(4, 512), 256, TF32GEMM_SMEM>>>(fgbuf, wc, bc, out,
                                                          TOKENS, 512, 1024);
}

// round 11
// speedup vs baseline: 2.3034x; 1.1168x over previous
#include <cuda_runtime.h>
#include <cuda_fp16.h>
#include <math_constants.h>
#include <cstdint>

// ---------------------------------------------------------------------------
// PFCAttention  (B=16, H=W=64, C=512, NH=16, hd=32, WS=8, TW=8)
// Round 11 (= Round 10 candidate, broker timeout): tcgen05 unavailable
// (harness builds compute_103 PTX, feature-gated).  Big GEMMs on fp16
// mma.sync.m16n8k16 (same 10-bit mantissa as tf32, 2x MAC/instr), cp.async
// 2-stage pipeline, conflict-free stride-20 smem.  Inputs converted to
// fp16-rn in pre-passes; attn writes fp16 FG.
// ---------------------------------------------------------------------------

#define TOKENS   65536
#define CDIM     512
#define NHEADS   16
#define HD       32
#define NTOK     64
#define NWIN     64
#define BATCH    16

// ------------------------- device scratch ----------------------------------
__device__ float  g_qkv[(size_t)TOKENS * 1536];
__device__ __half g_FGh[(size_t)TOKENS * 1024];   // [fine | coarse], fp16
__device__ __half g_xh[(size_t)TOKENS * 512];     // x in fp16
__device__ __half g_wt1[1536 * 512];              // qkv_w^T fp16
__device__ __half g_wt2[512 * 1024];              // Wc^T fp16
__device__ float  g_Kg[BATCH * NHEADS * NWIN * HD];
__device__ float  g_Vg[BATCH * NHEADS * NWIN * HD];
__device__ float  g_Wc[1024 * 512];
__device__ float  g_bc[512];
__device__ float  g_lb[NHEADS * NTOK * NTOK];
__device__ float  g_gb[NHEADS * NTOK * NWIN];

// ------------------------- helpers -----------------------------------------
__device__ __forceinline__ void cpa16(const void* smem_dst, const void* gsrc) {
    uint32_t dst = (uint32_t)__cvta_generic_to_shared(smem_dst);
    asm volatile("cp.async.cg.shared.global [%0], [%1], 16;"
                 :: "r"(dst), "l"(gsrc) : "memory");
}

__device__ __forceinline__ void mma_f16(float* c,
                                        uint32_t a0, uint32_t a1,
                                        uint32_t a2, uint32_t a3,
                                        uint32_t b0, uint32_t b1) {
    asm("mma.sync.aligned.m16n8k16.row.col.f32.f16.f16.f32 "
        "{%0,%1,%2,%3}, {%4,%5,%6,%7}, {%8,%9}, {%0,%1,%2,%3};"
        : "+f"(c[0]), "+f"(c[1]), "+f"(c[2]), "+f"(c[3])
        : "r"(a0), "r"(a1), "r"(a2), "r"(a3), "r"(b0), "r"(b1));
}

// ------------------------- pre-pass kernels --------------------------------
// float -> half (rn), 4 elems/thread
__global__ __launch_bounds__(256)
void f2h_kernel(const float4* __restrict__ in, __half2* __restrict__ out)
{
    int i = blockIdx.x * 256 + threadIdx.x;
    float4 v = in[i];
    out[2 * i + 0] = __floats2half2_rn(v.x, v.y);
    out[2 * i + 1] = __floats2half2_rn(v.z, v.w);
}

// transpose fp32 [R][C] -> fp16 [C][R]
__global__ __launch_bounds__(256)
void transpose_h_kernel(const float* __restrict__ in, __half* __restrict__ out,
                        int R, int C)
{
    __shared__ float t[32][33];
    int tx = threadIdx.x, ty = threadIdx.y;
    int c0 = blockIdx.x * 32, r0 = blockIdx.y * 32;
    #pragma unroll
    for (int j = ty; j < 32; j += 8)
        t[j][tx] = in[(size_t)(r0 + j) * C + c0 + tx];
    __syncthreads();
    #pragma unroll
    for (int j = ty; j < 32; j += 8)
        out[(size_t)(c0 + j) * R + r0 + tx] = __float2half_rn(t[tx][j]);
}

// ------------------------- bias table expansion ----------------------------
__global__ void expand_bias_kernel(const float* __restrict__ lt,
                                   const float* __restrict__ gt)
{
    int id = blockIdx.x * 256 + threadIdx.x;      // 512*256 = 131072
    int which = id >> 16;
    int r = id & 65535;
    int h = r >> 12;
    int n = (r >> 6) & 63;
    int m = r & 63;
    int i1 = n >> 3, j1 = n & 7;
    int i2 = m >> 3, j2 = m & 7;
    int idx = (i1 - i2 + 7) * 15 + (j1 - j2 + 7);
    if (which == 0) g_lb[r] = lt[idx * 16 + h];
    else            g_gb[r] = gt[idx * 16 + h];
}

// ------------------------- folded bias (parallel) --------------------------
__global__ __launch_bounds__(256)
void fold_bias_kernel(const float* __restrict__ lpb,
                      const float* __restrict__ gpb,
                      const float* __restrict__ pfw,
                      const float* __restrict__ pfb)
{
    __shared__ float red[256];
    int c = blockIdx.x;
    int t = threadIdx.x;
    float s = 0.0f;
    for (int j = t; j < 512; j += 256)
        s += lpb[j] * pfw[j * 512 + c] + gpb[j] * pfw[(512 + j) * 512 + c];
    red[t] = s;
    __syncthreads();
    for (int off = 128; off > 0; off >>= 1) {
        if (t < off) red[t] += red[t + off];
        __syncthreads();
    }
    if (t == 0) g_bc[c] = red[0] + pfb[c];
}

// ------------------------- fp32 SGEMM (small fold GEMMs only) --------------
__global__ __launch_bounds__(256)
void sgemm_kernel(const float* __restrict__ A,
                  const float* __restrict__ B,
                  const float* __restrict__ bias,
                  float* __restrict__ C,
                  int M, int N, int K)
{
    __shared__ float As[8][128];
    __shared__ float Bs[8][128];

    int tid = threadIdx.x;
    int bx = blockIdx.x, by = blockIdx.y;

    int aRow = tid >> 1;
    int aCol = (tid & 1) * 4;
    int bRow = tid >> 5;
    int bCol = (tid & 31) * 4;
    int tr = (tid >> 4) * 8;
    int tc = (tid & 15) * 8;

    const float* Ap = A + (size_t)(by * 128) * K;
    const float* Bp = B + bx * 128;

    float acc[8][8];
    #pragma unroll
    for (int i = 0; i < 8; i++)
        #pragma unroll
        for (int j = 0; j < 8; j++) acc[i][j] = 0.0f;

    for (int k0 = 0; k0 < K; k0 += 8) {
        float4 a = *(const float4*)(Ap + (size_t)aRow * K + k0 + aCol);
        As[aCol + 0][aRow] = a.x;
        As[aCol + 1][aRow] = a.y;
        As[aCol + 2][aRow] = a.z;
        As[aCol + 3][aRow] = a.w;
        *(float4*)&Bs[bRow][bCol] =
            *(const float4*)(Bp + (size_t)(k0 + bRow) * N + bCol);
        __syncthreads();

        #pragma unroll
        for (int kk = 0; kk < 8; kk++) {
            float ar[8], br[8];
            #pragma unroll
            for (int i = 0; i < 8; i++) ar[i] = As[kk][tr + i];
            #pragma unroll
            for (int j = 0; j < 8; j++) br[j] = Bs[kk][tc + j];
            #pragma unroll
            for (int i = 0; i < 8; i++)
                #pragma unroll
                for (int j = 0; j < 8; j++)
                    acc[i][j] += ar[i] * br[j];
        }
        __syncthreads();
    }

    #pragma unroll
    for (int i = 0; i < 8; i++) {
        size_t row = (size_t)(by * 128 + tr + i);
        #pragma unroll
        for (int j = 0; j < 8; j += 4) {
            float4 v;
            v.x = acc[i][j + 0];
            v.y = acc[i][j + 1];
            v.z = acc[i][j + 2];
            v.w = acc[i][j + 3];
            if (bias) {
                int col = bx * 128 + tc + j;
                v.x += bias[col + 0];
                v.y += bias[col + 1];
                v.z += bias[col + 2];
                v.w += bias[col + 3];
            }
            *(float4*)(C + row * N + bx * 128 + tc + j) = v;
        }
    }
}

// ------------------------- fp16 tensor-core GEMM ---------------------------
// C(MxN) = A(MxK) @ Bt(NxK)^T + bias.  A, Bt fp16 row-major (K contiguous).
// Block tile 128x128, k-tile 32 halves.  256 threads = 8 warps (2x4),
// warp tile 64x32.  Smem rows stride 20 words (16 data + 4 pad):
// bank(20g+tig) covers all 32 banks -> conflict-free fragment reads.
__global__ __launch_bounds__(256)
void hgemm_kernel(const __half* __restrict__ A,
                  const __half* __restrict__ Bt,
                  const float* __restrict__ bias,
                  float* __restrict__ C,
                  int M, int N, int K)
{
    __shared__ uint32_t As[2][128][20];
    __shared__ uint32_t Bs[2][128][20];

    const int tid  = threadIdx.x;
    const int warp = tid >> 5, lane = tid & 31;
    const int g = lane >> 2, tig = lane & 3;
    const int wm = warp >> 2, wn = warp & 3;       // 2 x 4 warp grid

    const __half* Ap = A + (size_t)(blockIdx.y * 128) * K;
    const __half* Bp = Bt + (size_t)(blockIdx.x * 128) * K;

    const int lrow = tid >> 1;                     // 0..127
    const int lc0 = (tid & 1) * 2;                 // chunks {lc0, lc0+1} of 4

    float acc[4][4][4];
    #pragma unroll
    for (int mt = 0; mt < 4; mt++)
        #pragma unroll
        for (int nt = 0; nt < 4; nt++)
            #pragma unroll
            for (int e = 0; e < 4; e++) acc[mt][nt][e] = 0.0f;

    const int NK = K >> 5;

    // prologue: tile 0 -> stage 0   (chunk c = 16B = 8 halves = 4 words)
    #pragma unroll
    for (int c = lc0; c < lc0 + 2; c++) {
        cpa16(&As[0][lrow][c * 4], Ap + (size_t)lrow * K + c * 8);
        cpa16(&Bs[0][lrow][c * 4], Bp + (size_t)lrow * K + c * 8);
    }
    asm volatile("cp.async.commit_group;" ::: "memory");

    for (int kt = 0; kt < NK; kt++) {
        const int cur = kt & 1;
        if (kt + 1 < NK) {
            const int nxt = cur ^ 1;
            const int k0 = (kt + 1) << 5;
            #pragma unroll
            for (int c = lc0; c < lc0 + 2; c++) {
                cpa16(&As[nxt][lrow][c * 4], Ap + (size_t)lrow * K + k0 + c * 8);
                cpa16(&Bs[nxt][lrow][c * 4], Bp + (size_t)lrow * K + k0 + c * 8);
            }
            asm volatile("cp.async.commit_group;" ::: "memory");
            asm volatile("cp.async.wait_group 1;" ::: "memory");
        } else {
            asm volatile("cp.async.wait_group 0;" ::: "memory");
        }
        __syncthreads();

        #pragma unroll
        for (int s = 0; s < 2; s++) {              // two k16 steps
            const int w0 = s * 8 + tig;            // word index k-low
            uint32_t a[4][4], b[4][2];
            #pragma unroll
            for (int mt = 0; mt < 4; mt++) {
                int r = wm * 64 + mt * 16 + g;
                a[mt][0] = As[cur][r][w0];
                a[mt][1] = As[cur][r + 8][w0];
                a[mt][2] = As[cur][r][w0 + 4];
                a[mt][3] = As[cur][r + 8][w0 + 4];
            }
            #pragma unroll
            for (int nt = 0; nt < 4; nt++) {
                int n = wn * 32 + nt * 8 + g;
                b[nt][0] = Bs[cur][n][w0];
                b[nt][1] = Bs[cur][n][w0 + 4];
            }
            #pragma unroll
            for (int mt = 0; mt < 4; mt++)
                #pragma unroll
                for (int nt = 0; nt < 4; nt++)
                    mma_f16(acc[mt][nt], a[mt][0], a[mt][1], a[mt][2], a[mt][3],
                            b[nt][0], b[nt][1]);
        }
        __syncthreads();
    }

    // epilogue:  c0,c1 -> (row g, cols 2tig..+1); c2,c3 -> (row g+8)
    #pragma unroll
    for (int mt = 0; mt < 4; mt++) {
        int row = blockIdx.y * 128 + wm * 64 + mt * 16 + g;
        #pragma unroll
        for (int nt = 0; nt < 4; nt++) {
            int col = blockIdx.x * 128 + wn * 32 + nt * 8 + tig * 2;
            float b0 = bias[col], b1 = bias[col + 1];
            float2 v0, v1;
            v0.x = acc[mt][nt][0] + b0; v0.y = acc[mt][nt][1] + b1;
            v1.x = acc[mt][nt][2] + b0; v1.y = acc[mt][nt][3] + b1;
            *(float2*)(C + (size_t)row * N + col) = v0;
            *(float2*)(C + (size_t)(row + 8) * N + col) = v1;
        }
    }
}

// ------------------------- pooled K,V --------------------------------------
__global__ __launch_bounds__(512)
void pool_kernel(const float* __restrict__ qkv,
                 const float* __restrict__ pool_w,
                 const float* __restrict__ pool_b)
{
    __shared__ float pw[64];
    int tid = threadIdx.x;
    if (tid < 64) pw[tid] = pool_w[tid];
    __syncthreads();

    int bw = blockIdx.x;
    int h = tid >> 5, d = tid & 31;
    const float* base = qkv + (size_t)bw * 64 * 1536 + h * 32 + d;

    float aK = 0.0f, aV = 0.0f;
    #pragma unroll 8
    for (int n = 0; n < 64; n++) {
        float w = pw[n];
        aK += base[n * 1536 + 512]  * w;
        aV += base[n * 1536 + 1024] * w;
    }
    float pb = pool_b[0];
    int b = bw >> 6, w_ = bw & 63;
    int o = ((b * 16 + h) * 64 + w_) * 32 + d;
    g_Kg[o] = aK + pb;
    g_Vg[o] = aV + pb;
}

// ------------------------- fused fine + coarse attention -------------------
__global__ __launch_bounds__(256)
void attn_kernel(const float* __restrict__ qkv, __half* __restrict__ FG)
{
    const int h  = blockIdx.x;
    const int b_ = blockIdx.y;
    const int b  = b_ >> 6;
    const int tid = threadIdx.x;

    __shared__ float sq[64 * 33];
    __shared__ float sk[64 * 33];
    __shared__ float sv[64 * 33];
    __shared__ float sP[64 * 65];

    const float scale = 0.17677669529663688f;

    const float* base = qkv + (size_t)b_ * 64 * 1536 + h * 32;
    #pragma unroll
    for (int i = 0; i < 8; i++) {
        int idx = i * 256 + tid;
        int n = idx >> 5, d = idx & 31;
        const float* p = base + (size_t)n * 1536 + d;
        sq[n * 33 + d] = p[0] * scale;
        sk[n * 33 + d] = p[512];
        sv[n * 33 + d] = p[1024];
    }
    __syncthreads();

    {
        const int tn = (tid >> 4) << 2;
        const int tm = (tid & 15) << 2;
        float acc[4][4];
        #pragma unroll
        for (int i = 0; i < 4; i++)
            #pragma unroll
            for (int j = 0; j < 4; j++) acc[i][j] = 0.0f;
        #pragma unroll
        for (int d = 0; d < 32; d++) {
            float qr[4], kr[4];
            #pragma unroll
            for (int i = 0; i < 4; i++) qr[i] = sq[(tn + i) * 33 + d];
            #pragma unroll
            for (int j = 0; j < 4; j++) kr[j] = sk[(tm + j) * 33 + d];
            #pragma unroll
            for (int i = 0; i < 4; i++)
                #pragma unroll
                for (int j = 0; j < 4; j++) acc[i][j] += qr[i] * kr[j];
        }
        const float* lb = g_lb + h * 4096;
        #pragma unroll
        for (int i = 0; i < 4; i++)
            #pragma unroll
            for (int j = 0; j < 4; j++)
                sP[(tn + i) * 65 + tm + j] = acc[i][j] + lb[(tn + i) * 64 + tm + j];
    }
    __syncthreads();

    if (tid < 64) {
        float mx = -CUDART_INF_F;
        #pragma unroll 8
        for (int m = 0; m < 64; m++) mx = fmaxf(mx, sP[tid * 65 + m]);
        float s = 0.0f;
        #pragma unroll 8
        for (int m = 0; m < 64; m++) {
            float e = __expf(sP[tid * 65 + m] - mx);
            sP[tid * 65 + m] = e;
            s += e;
        }
        float inv = 1.0f / s;
        #pragma unroll 8
        for (int m = 0; m < 64; m++) sP[tid * 65 + m] *= inv;
    }
    __syncthreads();

    __half* out = FG + (size_t)b_ * 64 * 1024 + h * 32;
    #pragma unroll
    for (int i = 0; i < 8; i++) {
        int idx = i * 256 + tid;
        int n = idx >> 5, d = idx & 31;
        float acc = 0.0f;
        #pragma unroll 8
        for (int m = 0; m < 64; m++) acc += sP[n * 65 + m] * sv[m * 33 + d];
        out[(size_t)n * 1024 + d] = __float2half_rn(acc);
    }
    __syncthreads();

    const float* kg = g_Kg + (size_t)((b * 16 + h) * 64) * 32;
    const float* vg = g_Vg + (size_t)((b * 16 + h) * 64) * 32;
    #pragma unroll
    for (int i = 0; i < 8; i++) {
        int idx = i * 256 + tid;
        int w = idx >> 5, d = idx & 31;
        sk[w * 33 + d] = kg[idx];
        sv[w * 33 + d] = vg[idx];
    }
    __syncthreads();

    {
        const int tn = (tid >> 4) << 2;
        const int tm = (tid & 15) << 2;
        float acc[4][4];
        #pragma unroll
        for (int i = 0; i < 4; i++)
            #pragma unroll
            for (int j = 0; j < 4; j++) acc[i][j] = 0.0f;
        #pragma unroll
        for (int d = 0; d < 32; d++) {
            float qr[4], kr[4];
            #pragma unroll
            for (int i = 0; i < 4; i++) qr[i] = sq[(tn + i) * 33 + d];
            #pragma unroll
            for (int j = 0; j < 4; j++) kr[j] = sk[(tm + j) * 33 + d];
            #pragma unroll
            for (int i = 0; i < 4; i++)
                #pragma unroll
                for (int j = 0; j < 4; j++) acc[i][j] += qr[i] * kr[j];
        }
        const float* gb = g_gb + h * 4096;
        #pragma unroll
        for (int i = 0; i < 4; i++)
            #pragma unroll
            for (int j = 0; j < 4; j++)
                sP[(tn + i) * 65 + tm + j] = acc[i][j] + gb[(tn + i) * 64 + tm + j];
    }
    __syncthreads();

    if (tid < 64) {
        float mx = -CUDART_INF_F;
        #pragma unroll 8
        for (int m = 0; m < 64; m++) mx = fmaxf(mx, sP[tid * 65 + m]);
        float s = 0.0f;
        #pragma unroll 8
        for (int m = 0; m < 64; m++) {
            float e = __expf(sP[tid * 65 + m] - mx);
            sP[tid * 65 + m] = e;
            s += e;
        }
        float inv = 1.0f / s;
        #pragma unroll 8
        for (int m = 0; m < 64; m++) sP[tid * 65 + m] *= inv;
    }
    __syncthreads();

    #pragma unroll
    for (int i = 0; i < 8; i++) {
        int idx = i * 256 + tid;
        int n = idx >> 5, d = idx & 31;
        float acc = 0.0f;
        #pragma unroll 8
        for (int m = 0; m < 64; m++) acc += sP[n * 65 + m] * sv[m * 33 + d];
        out[(size_t)n * 1024 + 512 + d] = __float2half_rn(acc);
    }
}

// ------------------------- launch ------------------------------------------
extern "C" void kernel_launch(void* const* d_in, const int* in_sizes, int n_in,
                              void* d_out, int out_size)
{
    const float* x     = (const float*)d_in[0];
    const float* qkv_w = (const float*)d_in[1];
    const float* qkv_b = (const float*)d_in[2];
    const float* lbt   = (const float*)d_in[3];
    const float* gbt   = (const float*)d_in[4];
    const float* lpw   = (const float*)d_in[5];
    const float* lpb   = (const float*)d_in[6];
    const float* pw    = (const float*)d_in[7];
    const float* pb    = (const float*)d_in[8];
    const float* gpw   = (const float*)d_in[9];
    const float* gpb   = (const float*)d_in[10];
    const float* pfw   = (const float*)d_in[11];
    const float* pfb   = (const float*)d_in[12];
    float* out = (float*)d_out;

    float *qkvbuf, *wc, *bc;
    __half *fgh, *xh, *wt1, *wt2;
    cudaGetSymbolAddress((void**)&qkvbuf, g_qkv);
    cudaGetSymbolAddress((void**)&fgh,    g_FGh);
    cudaGetSymbolAddress((void**)&xh,     g_xh);
    cudaGetSymbolAddress((void**)&wt1,    g_wt1);
    cudaGetSymbolAddress((void**)&wt2,    g_wt2);
    cudaGetSymbolAddress((void**)&wc,     g_Wc);
    cudaGetSymbolAddress((void**)&bc,     g_bc);

    // 1) x -> fp16
    f2h_kernel<<<32768, 256>>>((const float4*)x, (__half2*)xh);
    // 2) qkv_w (512x1536) -> transposed fp16 (1536x512)
    transpose_h_kernel<<<dim3(48, 16), dim3(32, 8)>>>(qkv_w, wt1, 512, 1536);
    // 3) bias tables
    expand_bias_kernel<<<512, 256>>>(lbt, gbt);
    // 4-5) fold projections into Wc (fp32)
    sgemm_kernel<<<dim3(4, 4), 256>>>(lpw, pfw,             nullptr, wc,             512, 512, 512);
    sgemm_kernel<<<dim3(4, 4), 256>>>(gpw, pfw + 512 * 512, nullptr, wc + 512 * 512, 512, 512, 512);
    // 6) qkv GEMM on fp16 tensor cores   (launch #6 -> ncu -s 5 lands here)
    hgemm_kernel<<<dim3(12, 512), 256>>>(xh, wt1, qkv_b, qkvbuf, TOKENS, 1536, 512);
    // 7) folded bias
    fold_bias_kernel<<<512, 256>>>(lpb, gpb, pfw, pfb);
    // 8) Wc (1024x512) -> transposed fp16 (512x1024)
    transpose_h_kernel<<<dim3(16, 32), dim3(32, 8)>>>(wc, wt2, 1024, 512);
    // 9) pooled K,V
    pool_kernel<<<1024, 512>>>(qkvbuf, pw, pb);
    // 10) fused fine + coarse attention (writes fp16 FG)
    attn_kernel<<<dim3(16, 1024), 256>>>(qkvbuf, fgh);
    // 11) final fused projection on fp16 tensor cores
    hgemm_kernel<<<dim3(4, 512), 256>>>(fgh, wt2, bc, out, TOKENS, 512, 1024);
}